// round 1
// baseline (speedup 1.0000x reference)
#include <cuda_runtime.h>
#include <cfloat>
#include <math.h>

// Problem constants
#define BB 4
#define SS 2048
#define DD 1024
#define HH 16
#define HD 64
#define MM (BB*SS)   // 8192

// Scratch (static device arrays; allocation-free per harness rules)
__device__ float g_qp[BB*SS*DD];  // Q projection; reused as Wo-GEMM output
__device__ float g_kp[BB*SS*DD];
__device__ float g_vp[BB*SS*DD];
__device__ float g_ao[BB*SS*DD];  // attention output

// ---------------------------------------------------------------------------
// SGEMM (NT): C[M,N] = A[M,K] @ W[N,K]^T + bias[N]
// 128x128 block, BK=8, 256 threads, 8x8 micro-tile per thread.
// ---------------------------------------------------------------------------
__global__ __launch_bounds__(256) void sgemm_nt(
    const float* __restrict__ A, const float* __restrict__ W,
    const float* __restrict__ bias, float* __restrict__ C,
    int M, int N, int K)
{
    __shared__ float As[8][128];
    __shared__ float Ws[8][128];
    const int tid = threadIdx.x;
    const int bm = blockIdx.y * 128;
    const int bn = blockIdx.x * 128;
    const int lrow = tid >> 1;          // 0..127
    const int lq   = (tid & 1) << 2;    // 0 or 4
    const int tx = tid & 15, ty = tid >> 4;

    const float* Ag = A + (size_t)(bm + lrow) * K + lq;
    const float* Wg = W + (size_t)(bn + lrow) * K + lq;

    float acc[8][8];
#pragma unroll
    for (int i = 0; i < 8; i++)
#pragma unroll
        for (int j = 0; j < 8; j++) acc[i][j] = 0.f;

    for (int k0 = 0; k0 < K; k0 += 8) {
        float4 av = *(const float4*)(Ag + k0);
        float4 wv = *(const float4*)(Wg + k0);
        __syncthreads();
        As[lq+0][lrow] = av.x; As[lq+1][lrow] = av.y;
        As[lq+2][lrow] = av.z; As[lq+3][lrow] = av.w;
        Ws[lq+0][lrow] = wv.x; Ws[lq+1][lrow] = wv.y;
        Ws[lq+2][lrow] = wv.z; Ws[lq+3][lrow] = wv.w;
        __syncthreads();
#pragma unroll
        for (int kk = 0; kk < 8; kk++) {
            float a[8], bb[8];
            *(float4*)&a[0]  = *(const float4*)&As[kk][ty*4];
            *(float4*)&a[4]  = *(const float4*)&As[kk][64 + ty*4];
            *(float4*)&bb[0] = *(const float4*)&Ws[kk][tx*4];
            *(float4*)&bb[4] = *(const float4*)&Ws[kk][64 + tx*4];
#pragma unroll
            for (int i = 0; i < 8; i++)
#pragma unroll
                for (int j = 0; j < 8; j++)
                    acc[i][j] += a[i] * bb[j];
        }
    }

#pragma unroll
    for (int ih = 0; ih < 2; ih++)
#pragma unroll
    for (int i = 0; i < 4; i++) {
        int row = bm + ih*64 + ty*4 + i;
        float* Cr = C + (size_t)row * N + bn;
#pragma unroll
        for (int jh = 0; jh < 2; jh++) {
            int col = jh*64 + tx*4;
            float4 bv = *(const float4*)(bias + bn + col);
            float4 o;
            o.x = acc[ih*4+i][jh*4+0] + bv.x;
            o.y = acc[ih*4+i][jh*4+1] + bv.y;
            o.z = acc[ih*4+i][jh*4+2] + bv.z;
            o.w = acc[ih*4+i][jh*4+3] + bv.w;
            *(float4*)(Cr + col) = o;
        }
    }
}

// ---------------------------------------------------------------------------
// Flash attention (fp32, causal + pad mask, scale folded into Q).
// Grid: (S/64, H, B). 256 threads. Thread (tx,ty) owns 4 rows (ty*4..),
// 4 keys (tx + 16*jj) for scores, 4 output cols (tx*4..) for PV.
// Dynamic smem: Qs[64][64] | Ks[64][68] | Vs[64][64] | Ps[64][68]
// ---------------------------------------------------------------------------
#define ATTN_SMEM ((64*64 + 64*68 + 64*64 + 64*68) * 4)

__global__ __launch_bounds__(256) void attn_kernel(
    const float* __restrict__ QP, const float* __restrict__ KP,
    const float* __restrict__ VP, const int* __restrict__ pad,
    float* __restrict__ O)
{
    extern __shared__ float smem[];
    float* Qs = smem;                 // [64][64]
    float* Ks = Qs + 64*64;           // [64][68]
    float* Vs = Ks + 64*68;           // [64][64]
    float* Ps = Vs + 64*64;           // [64][68]

    const int qt = blockIdx.x;
    const int h  = blockIdx.y;
    const int b  = blockIdx.z;
    const int tid = threadIdx.x;
    const int tx = tid & 15, ty = tid >> 4;
    const size_t base = (size_t)b * SS * DD + (size_t)h * SS * HD;
    const int* padb = pad + b * SS;

    // Load Q tile, pre-scaled by 1/sqrt(HD)
    for (int i = tid; i < 64*16; i += 256) {
        int r = i >> 4, c = (i & 15) << 2;
        float4 v = *(const float4*)(QP + base + (size_t)(qt*64 + r) * HD + c);
        v.x *= 0.125f; v.y *= 0.125f; v.z *= 0.125f; v.w *= 0.125f;
        *(float4*)(Qs + r*64 + c) = v;
    }

    float m[4], l[4], acc[4][4];
#pragma unroll
    for (int i = 0; i < 4; i++) {
        m[i] = -FLT_MAX; l[i] = 0.f;
#pragma unroll
        for (int c = 0; c < 4; c++) acc[i][c] = 0.f;
    }

    for (int j = 0; j <= qt; j++) {
        __syncthreads();   // protect Ks/Vs/Ps from previous iteration readers
        for (int i = tid; i < 64*16; i += 256) {
            int r = i >> 4, c = (i & 15) << 2;
            float4 kv = *(const float4*)(KP + base + (size_t)(j*64 + r) * HD + c);
            float4 vv = *(const float4*)(VP + base + (size_t)(j*64 + r) * HD + c);
            *(float4*)(Ks + r*68 + c) = kv;
            *(float4*)(Vs + r*64 + c) = vv;
        }
        __syncthreads();

        // --- scores: s[i][jj] = (Q row ty*4+i) . (K row tx+16*jj) ---
        float s[4][4];
#pragma unroll
        for (int i = 0; i < 4; i++)
#pragma unroll
            for (int jj = 0; jj < 4; jj++) s[i][jj] = 0.f;

#pragma unroll 4
        for (int d = 0; d < 64; d += 4) {
            float4 q4[4], k4[4];
#pragma unroll
            for (int i = 0; i < 4; i++)
                q4[i] = *(const float4*)(Qs + (ty*4 + i)*64 + d);
#pragma unroll
            for (int jj = 0; jj < 4; jj++)
                k4[jj] = *(const float4*)(Ks + (tx + jj*16)*68 + d);
#pragma unroll
            for (int i = 0; i < 4; i++)
#pragma unroll
                for (int jj = 0; jj < 4; jj++)
                    s[i][jj] += q4[i].x*k4[jj].x + q4[i].y*k4[jj].y
                              + q4[i].z*k4[jj].z + q4[i].w*k4[jj].w;
        }

        // --- masking (pad + causal), reference applies before scaling;
        //     Q was pre-scaled which is equivalent since -inf is invariant ---
#pragma unroll
        for (int jj = 0; jj < 4; jj++) {
            int kidx = j*64 + tx + jj*16;
            int pm = padb[kidx];
#pragma unroll
            for (int i = 0; i < 4; i++) {
                int qidx = qt*64 + ty*4 + i;
                if (pm == 0 || kidx > qidx) s[i][jj] = -FLT_MAX;
            }
        }

        // --- online softmax update (row shared across 16 tx lanes) ---
#pragma unroll
        for (int i = 0; i < 4; i++) {
            float mt = fmaxf(fmaxf(s[i][0], s[i][1]), fmaxf(s[i][2], s[i][3]));
#pragma unroll
            for (int o = 1; o < 16; o <<= 1)
                mt = fmaxf(mt, __shfl_xor_sync(0xffffffffu, mt, o));
            float mn = fmaxf(m[i], mt);
            float corr = __expf(m[i] - mn);
            float rs = 0.f;
#pragma unroll
            for (int jj = 0; jj < 4; jj++) {
                float p = __expf(s[i][jj] - mn);
                s[i][jj] = p;
                rs += p;
            }
#pragma unroll
            for (int o = 1; o < 16; o <<= 1)
                rs += __shfl_xor_sync(0xffffffffu, rs, o);
            l[i] = l[i] * corr + rs;
            m[i] = mn;
#pragma unroll
            for (int c = 0; c < 4; c++) acc[i][c] *= corr;
        }

        // stage probabilities: Ps[key][row]
#pragma unroll
        for (int jj = 0; jj < 4; jj++)
#pragma unroll
            for (int i = 0; i < 4; i++)
                Ps[(tx + jj*16)*68 + ty*4 + i] = s[i][jj];
        __syncthreads();

        // --- PV: acc[i][c] += sum_key Ps[key][ty*4+i] * Vs[key][tx*4+c] ---
#pragma unroll 8
        for (int key = 0; key < 64; key++) {
            float4 pr = *(const float4*)(Ps + key*68 + ty*4);
            float4 vv = *(const float4*)(Vs + key*64 + tx*4);
            float p4[4] = {pr.x, pr.y, pr.z, pr.w};
            float v4[4] = {vv.x, vv.y, vv.z, vv.w};
#pragma unroll
            for (int i = 0; i < 4; i++)
#pragma unroll
                for (int c = 0; c < 4; c++)
                    acc[i][c] += p4[i] * v4[c];
        }
    }

    // epilogue: normalize and store
#pragma unroll
    for (int i = 0; i < 4; i++) {
        float inv = 1.f / l[i];
        float4 o;
        o.x = acc[i][0] * inv;
        o.y = acc[i][1] * inv;
        o.z = acc[i][2] * inv;
        o.w = acc[i][3] * inv;
        *(float4*)(O + base + (size_t)(qt*64 + ty*4 + i) * HD + tx*4) = o;
    }
}

// ---------------------------------------------------------------------------
// Residual add + LayerNorm: out = gamma*(y-mean)/(std+1e-8)+beta, y = x + yo
// One block per row of D=1024, 256 threads x 4 elems.
// ---------------------------------------------------------------------------
__global__ __launch_bounds__(256) void ln_kernel(
    const float* __restrict__ X, const float* __restrict__ Yo,
    const float* __restrict__ gamma, const float* __restrict__ beta,
    float* __restrict__ out)
{
    const int row = blockIdx.x;
    const int tid = threadIdx.x;
    const size_t off = (size_t)row * DD + tid * 4;
    float4 xv = *(const float4*)(X + off);
    float4 yv = *(const float4*)(Yo + off);
    float v[4] = {xv.x + yv.x, xv.y + yv.y, xv.z + yv.z, xv.w + yv.w};
    float s  = v[0] + v[1] + v[2] + v[3];
    float sq = v[0]*v[0] + v[1]*v[1] + v[2]*v[2] + v[3]*v[3];
#pragma unroll
    for (int o = 16; o; o >>= 1) {
        s  += __shfl_xor_sync(0xffffffffu, s,  o);
        sq += __shfl_xor_sync(0xffffffffu, sq, o);
    }
    __shared__ float ssum[8], ssq[8];
    if ((tid & 31) == 0) { ssum[tid >> 5] = s; ssq[tid >> 5] = sq; }
    __syncthreads();
    s = 0.f; sq = 0.f;
#pragma unroll
    for (int i = 0; i < 8; i++) { s += ssum[i]; sq += ssq[i]; }
    float mean = s * (1.f / DD);
    float var  = sq * (1.f / DD) - mean * mean;
    float rstd = 1.f / (sqrtf(fmaxf(var, 0.f)) + 1e-8f);
    int c = tid * 4;
    float4 g  = *(const float4*)(gamma + c);
    float4 bt = *(const float4*)(beta + c);
    float4 o;
    o.x = g.x * (v[0] - mean) * rstd + bt.x;
    o.y = g.y * (v[1] - mean) * rstd + bt.y;
    o.z = g.z * (v[2] - mean) * rstd + bt.z;
    o.w = g.w * (v[3] - mean) * rstd + bt.w;
    *(float4*)(out + off) = o;
}

// ---------------------------------------------------------------------------
extern "C" void kernel_launch(void* const* d_in, const int* in_sizes, int n_in,
                              void* d_out, int out_size)
{
    const float* q     = (const float*)d_in[0];
    const float* k     = (const float*)d_in[1];
    const float* v     = (const float*)d_in[2];
    // d_in[3] = attn_mask (deterministic causal tril) — computed analytically
    const int*   pad   = (const int*)d_in[4];
    const float* Wq    = (const float*)d_in[5];
    const float* bq    = (const float*)d_in[6];
    const float* Wk    = (const float*)d_in[7];
    const float* bk    = (const float*)d_in[8];
    const float* Wv    = (const float*)d_in[9];
    const float* bv    = (const float*)d_in[10];
    const float* Wo    = (const float*)d_in[11];
    const float* bo    = (const float*)d_in[12];
    const float* gamma = (const float*)d_in[13];
    const float* beta  = (const float*)d_in[14];
    float* out = (float*)d_out;

    float *qp, *kp, *vp, *ao;
    cudaGetSymbolAddress((void**)&qp, g_qp);
    cudaGetSymbolAddress((void**)&kp, g_kp);
    cudaGetSymbolAddress((void**)&vp, g_vp);
    cudaGetSymbolAddress((void**)&ao, g_ao);

    cudaFuncSetAttribute(attn_kernel,
                         cudaFuncAttributeMaxDynamicSharedMemorySize, ATTN_SMEM);

    dim3 gg(DD / 128, MM / 128);  // (8, 64)
    sgemm_nt<<<gg, 256>>>(q, Wq, bq, qp, MM, DD, DD);
    sgemm_nt<<<gg, 256>>>(k, Wk, bk, kp, MM, DD, DD);
    sgemm_nt<<<gg, 256>>>(v, Wv, bv, vp, MM, DD, DD);

    attn_kernel<<<dim3(SS / 64, HH, BB), 256, ATTN_SMEM>>>(qp, kp, vp, pad, ao);

    // Wo projection: reuse g_qp as output (qp no longer needed)
    sgemm_nt<<<gg, 256>>>(ao, Wo, bo, qp, MM, DD, DD);

    ln_kernel<<<MM, 256>>>(q, qp, gamma, beta, out);
}

// round 2
// speedup vs baseline: 1.0938x; 1.0938x over previous
#include <cuda_runtime.h>
#include <cuda_bf16.h>
#include <cfloat>
#include <math.h>
#include <stdint.h>

// Problem constants
#define BB 4
#define SS 2048
#define DD 1024
#define HH 16
#define HD 64
#define MM (BB*SS)   // 8192

// Scratch (static device arrays; allocation-free per harness rules)
__device__ float g_qp[BB*SS*DD];  // Q projection; reused as Wo-GEMM output
__device__ float g_kp[BB*SS*DD];
__device__ float g_vp[BB*SS*DD];
__device__ float g_ao[BB*SS*DD];  // attention output

// ---------------------------------------------------------------------------
// Split-bf16 tensor-core GEMM (NT): C[M,N] = A[M,K] @ W[N,K]^T + bias[N]
// fp32 operands decomposed as hi(bf16)+lo(bf16); C ≈ hh + hl + lh (fp32 acc).
// 128x128 block, BK=32, 256 threads (8 warps), warp tile 32x64,
// mma.sync.aligned.m16n8k16.row.col.f32.bf16.bf16.f32
// ---------------------------------------------------------------------------
#define SMSTR 40   // smem row stride in halves (32 data + 8 pad)

#define MMA16816(d, a, b0v, b1v) \
    asm volatile("mma.sync.aligned.m16n8k16.row.col.f32.bf16.bf16.f32 " \
        "{%0,%1,%2,%3}, {%4,%5,%6,%7}, {%8,%9}, {%0,%1,%2,%3};\n" \
        : "+f"((d)[0]), "+f"((d)[1]), "+f"((d)[2]), "+f"((d)[3]) \
        : "r"((a)[0]), "r"((a)[1]), "r"((a)[2]), "r"((a)[3]), \
          "r"(b0v), "r"(b1v))

__device__ __forceinline__ void load_pack16(const float* __restrict__ g,
                                            uint32_t* __restrict__ p)
{
#pragma unroll
    for (int i = 0; i < 16; i += 4) {
        float4 v = *(const float4*)(g + i);
        float xs[4] = {v.x, v.y, v.z, v.w};
#pragma unroll
        for (int j = 0; j < 4; j++) {
            float x = xs[j];
            __nv_bfloat16 h = __float2bfloat16(x);
            float hf = __bfloat162float(h);
            __nv_bfloat16 l = __float2bfloat16(x - hf);
            p[i + j] = (uint32_t)__bfloat16_as_ushort(h)
                     | ((uint32_t)__bfloat16_as_ushort(l) << 16);
        }
    }
}

__global__ __launch_bounds__(256) void gemm_bf16x3(
    const float* __restrict__ A, const float* __restrict__ W,
    const float* __restrict__ bias, float* __restrict__ C,
    int M, int N, int K)
{
    __shared__ __nv_bfloat16 Ah[128][SMSTR], Al[128][SMSTR];
    __shared__ __nv_bfloat16 Wh[128][SMSTR], Wl[128][SMSTR];

    const int tid = threadIdx.x;
    const int bm = blockIdx.y * 128;
    const int bn = blockIdx.x * 128;
    const int lrow = tid >> 1;
    const int lcol = (tid & 1) * 16;

    const float* Ag = A + (size_t)(bm + lrow) * K + lcol;
    const float* Wg = W + (size_t)(bn + lrow) * K + lcol;

    const int warp = tid >> 5, lane = tid & 31;
    const int wm = (warp >> 1) * 32;   // warp M offset (4 warps along M)
    const int wn = (warp & 1) * 64;    // warp N offset (2 warps along N)
    const int lr = lane >> 2;          // 0..7
    const int lc2 = (lane & 3) * 2;    // 0,2,4,6

    float acc[2][8][4];
#pragma unroll
    for (int mi = 0; mi < 2; mi++)
#pragma unroll
        for (int ni = 0; ni < 8; ni++)
#pragma unroll
            for (int c = 0; c < 4; c++) acc[mi][ni][c] = 0.f;

    uint32_t pa[16], pw[16];
    load_pack16(Ag, pa);
    load_pack16(Wg, pw);

    for (int k0 = 0; k0 < K; k0 += 32) {
        // stage packed hi/lo into smem (u32 = two adjacent halves)
#pragma unroll
        for (int i = 0; i < 16; i += 2) {
            uint32_t ha = (pa[i] & 0xffffu) | (pa[i+1] << 16);
            uint32_t la = (pa[i] >> 16)     | (pa[i+1] & 0xffff0000u);
            uint32_t hw = (pw[i] & 0xffffu) | (pw[i+1] << 16);
            uint32_t lw = (pw[i] >> 16)     | (pw[i+1] & 0xffff0000u);
            *(uint32_t*)&Ah[lrow][lcol + i] = ha;
            *(uint32_t*)&Al[lrow][lcol + i] = la;
            *(uint32_t*)&Wh[lrow][lcol + i] = hw;
            *(uint32_t*)&Wl[lrow][lcol + i] = lw;
        }
        __syncthreads();

        if (k0 + 32 < K) {           // prefetch next slice
            load_pack16(Ag + k0 + 32, pa);
            load_pack16(Wg + k0 + 32, pw);
        }

#pragma unroll
        for (int kk = 0; kk < 32; kk += 16) {
            uint32_t ah[2][4], al[2][4];
#pragma unroll
            for (int mi = 0; mi < 2; mi++) {
                int r = wm + mi * 16 + lr;
                int c = kk + lc2;
                ah[mi][0] = *(const uint32_t*)&Ah[r    ][c    ];
                ah[mi][1] = *(const uint32_t*)&Ah[r + 8][c    ];
                ah[mi][2] = *(const uint32_t*)&Ah[r    ][c + 8];
                ah[mi][3] = *(const uint32_t*)&Ah[r + 8][c + 8];
                al[mi][0] = *(const uint32_t*)&Al[r    ][c    ];
                al[mi][1] = *(const uint32_t*)&Al[r + 8][c    ];
                al[mi][2] = *(const uint32_t*)&Al[r    ][c + 8];
                al[mi][3] = *(const uint32_t*)&Al[r + 8][c + 8];
            }
#pragma unroll
            for (int ni = 0; ni < 8; ni++) {
                int n = wn + ni * 8 + lr;
                int ck = kk + lc2;
                uint32_t bh0 = *(const uint32_t*)&Wh[n][ck    ];
                uint32_t bh1 = *(const uint32_t*)&Wh[n][ck + 8];
                uint32_t bl0 = *(const uint32_t*)&Wl[n][ck    ];
                uint32_t bl1 = *(const uint32_t*)&Wl[n][ck + 8];
#pragma unroll
                for (int mi = 0; mi < 2; mi++) {
                    MMA16816(acc[mi][ni], ah[mi], bh0, bh1);  // hi*hi
                    MMA16816(acc[mi][ni], al[mi], bh0, bh1);  // lo*hi
                    MMA16816(acc[mi][ni], ah[mi], bl0, bl1);  // hi*lo
                }
            }
        }
        __syncthreads();
    }

    // epilogue: fp32 + bias
#pragma unroll
    for (int mi = 0; mi < 2; mi++) {
#pragma unroll
        for (int ni = 0; ni < 8; ni++) {
            int row = bm + wm + mi * 16 + lr;
            int col = bn + wn + ni * 8 + lc2;
            float b0 = bias[col], b1 = bias[col + 1];
            float2 o0 = {acc[mi][ni][0] + b0, acc[mi][ni][1] + b1};
            float2 o1 = {acc[mi][ni][2] + b0, acc[mi][ni][3] + b1};
            *(float2*)(C + (size_t)row * N + col)       = o0;
            *(float2*)(C + (size_t)(row + 8) * N + col) = o1;
        }
    }
}

// ---------------------------------------------------------------------------
// Flash attention (fp32, causal + pad mask, scale folded into Q).
// Grid: (S/64, H, B). 256 threads. Thread (tx,ty) owns 4 rows (ty*4..),
// 4 keys (tx + 16*jj) for scores, 4 output cols (tx*4..) for PV.
// Dynamic smem: Qs[64][64] | Ks[64][68] | Vs[64][64] | Ps[64][68]
// ---------------------------------------------------------------------------
#define ATTN_SMEM ((64*64 + 64*68 + 64*64 + 64*68) * 4)

__global__ __launch_bounds__(256) void attn_kernel(
    const float* __restrict__ QP, const float* __restrict__ KP,
    const float* __restrict__ VP, const int* __restrict__ pad,
    float* __restrict__ O)
{
    extern __shared__ float smem[];
    float* Qs = smem;                 // [64][64]
    float* Ks = Qs + 64*64;           // [64][68]
    float* Vs = Ks + 64*68;           // [64][64]
    float* Ps = Vs + 64*64;           // [64][68]

    const int qt = blockIdx.x;
    const int h  = blockIdx.y;
    const int b  = blockIdx.z;
    const int tid = threadIdx.x;
    const int tx = tid & 15, ty = tid >> 4;
    const size_t base = (size_t)b * SS * DD + (size_t)h * SS * HD;
    const int* padb = pad + b * SS;

    for (int i = tid; i < 64*16; i += 256) {
        int r = i >> 4, c = (i & 15) << 2;
        float4 v = *(const float4*)(QP + base + (size_t)(qt*64 + r) * HD + c);
        v.x *= 0.125f; v.y *= 0.125f; v.z *= 0.125f; v.w *= 0.125f;
        *(float4*)(Qs + r*64 + c) = v;
    }

    float m[4], l[4], acc[4][4];
#pragma unroll
    for (int i = 0; i < 4; i++) {
        m[i] = -FLT_MAX; l[i] = 0.f;
#pragma unroll
        for (int c = 0; c < 4; c++) acc[i][c] = 0.f;
    }

    for (int j = 0; j <= qt; j++) {
        __syncthreads();
        for (int i = tid; i < 64*16; i += 256) {
            int r = i >> 4, c = (i & 15) << 2;
            float4 kv = *(const float4*)(KP + base + (size_t)(j*64 + r) * HD + c);
            float4 vv = *(const float4*)(VP + base + (size_t)(j*64 + r) * HD + c);
            *(float4*)(Ks + r*68 + c) = kv;
            *(float4*)(Vs + r*64 + c) = vv;
        }
        __syncthreads();

        float s[4][4];
#pragma unroll
        for (int i = 0; i < 4; i++)
#pragma unroll
            for (int jj = 0; jj < 4; jj++) s[i][jj] = 0.f;

#pragma unroll 4
        for (int d = 0; d < 64; d += 4) {
            float4 q4[4], k4[4];
#pragma unroll
            for (int i = 0; i < 4; i++)
                q4[i] = *(const float4*)(Qs + (ty*4 + i)*64 + d);
#pragma unroll
            for (int jj = 0; jj < 4; jj++)
                k4[jj] = *(const float4*)(Ks + (tx + jj*16)*68 + d);
#pragma unroll
            for (int i = 0; i < 4; i++)
#pragma unroll
                for (int jj = 0; jj < 4; jj++)
                    s[i][jj] += q4[i].x*k4[jj].x + q4[i].y*k4[jj].y
                              + q4[i].z*k4[jj].z + q4[i].w*k4[jj].w;
        }

#pragma unroll
        for (int jj = 0; jj < 4; jj++) {
            int kidx = j*64 + tx + jj*16;
            int pm = padb[kidx];
#pragma unroll
            for (int i = 0; i < 4; i++) {
                int qidx = qt*64 + ty*4 + i;
                if (pm == 0 || kidx > qidx) s[i][jj] = -FLT_MAX;
            }
        }

#pragma unroll
        for (int i = 0; i < 4; i++) {
            float mt = fmaxf(fmaxf(s[i][0], s[i][1]), fmaxf(s[i][2], s[i][3]));
#pragma unroll
            for (int o = 1; o < 16; o <<= 1)
                mt = fmaxf(mt, __shfl_xor_sync(0xffffffffu, mt, o));
            float mn = fmaxf(m[i], mt);
            float corr = __expf(m[i] - mn);
            float rs = 0.f;
#pragma unroll
            for (int jj = 0; jj < 4; jj++) {
                float p = __expf(s[i][jj] - mn);
                s[i][jj] = p;
                rs += p;
            }
#pragma unroll
            for (int o = 1; o < 16; o <<= 1)
                rs += __shfl_xor_sync(0xffffffffu, rs, o);
            l[i] = l[i] * corr + rs;
            m[i] = mn;
#pragma unroll
            for (int c = 0; c < 4; c++) acc[i][c] *= corr;
        }

#pragma unroll
        for (int jj = 0; jj < 4; jj++)
#pragma unroll
            for (int i = 0; i < 4; i++)
                Ps[(tx + jj*16)*68 + ty*4 + i] = s[i][jj];
        __syncthreads();

#pragma unroll 8
        for (int key = 0; key < 64; key++) {
            float4 pr = *(const float4*)(Ps + key*68 + ty*4);
            float4 vv = *(const float4*)(Vs + key*64 + tx*4);
            float p4[4] = {pr.x, pr.y, pr.z, pr.w};
            float v4[4] = {vv.x, vv.y, vv.z, vv.w};
#pragma unroll
            for (int i = 0; i < 4; i++)
#pragma unroll
                for (int c = 0; c < 4; c++)
                    acc[i][c] += p4[i] * v4[c];
        }
    }

#pragma unroll
    for (int i = 0; i < 4; i++) {
        float inv = 1.f / l[i];
        float4 o;
        o.x = acc[i][0] * inv;
        o.y = acc[i][1] * inv;
        o.z = acc[i][2] * inv;
        o.w = acc[i][3] * inv;
        *(float4*)(O + base + (size_t)(qt*64 + ty*4 + i) * HD + tx*4) = o;
    }
}

// ---------------------------------------------------------------------------
// Residual add + LayerNorm
// ---------------------------------------------------------------------------
__global__ __launch_bounds__(256) void ln_kernel(
    const float* __restrict__ X, const float* __restrict__ Yo,
    const float* __restrict__ gamma, const float* __restrict__ beta,
    float* __restrict__ out)
{
    const int row = blockIdx.x;
    const int tid = threadIdx.x;
    const size_t off = (size_t)row * DD + tid * 4;
    float4 xv = *(const float4*)(X + off);
    float4 yv = *(const float4*)(Yo + off);
    float v[4] = {xv.x + yv.x, xv.y + yv.y, xv.z + yv.z, xv.w + yv.w};
    float s  = v[0] + v[1] + v[2] + v[3];
    float sq = v[0]*v[0] + v[1]*v[1] + v[2]*v[2] + v[3]*v[3];
#pragma unroll
    for (int o = 16; o; o >>= 1) {
        s  += __shfl_xor_sync(0xffffffffu, s,  o);
        sq += __shfl_xor_sync(0xffffffffu, sq, o);
    }
    __shared__ float ssum[8], ssq[8];
    if ((tid & 31) == 0) { ssum[tid >> 5] = s; ssq[tid >> 5] = sq; }
    __syncthreads();
    s = 0.f; sq = 0.f;
#pragma unroll
    for (int i = 0; i < 8; i++) { s += ssum[i]; sq += ssq[i]; }
    float mean = s * (1.f / DD);
    float var  = sq * (1.f / DD) - mean * mean;
    float rstd = 1.f / (sqrtf(fmaxf(var, 0.f)) + 1e-8f);
    int c = tid * 4;
    float4 g  = *(const float4*)(gamma + c);
    float4 bt = *(const float4*)(beta + c);
    float4 o;
    o.x = g.x * (v[0] - mean) * rstd + bt.x;
    o.y = g.y * (v[1] - mean) * rstd + bt.y;
    o.z = g.z * (v[2] - mean) * rstd + bt.z;
    o.w = g.w * (v[3] - mean) * rstd + bt.w;
    *(float4*)(out + off) = o;
}

// ---------------------------------------------------------------------------
extern "C" void kernel_launch(void* const* d_in, const int* in_sizes, int n_in,
                              void* d_out, int out_size)
{
    const float* q     = (const float*)d_in[0];
    const float* k     = (const float*)d_in[1];
    const float* v     = (const float*)d_in[2];
    // d_in[3] = attn_mask (deterministic causal tril) — computed analytically
    const int*   pad   = (const int*)d_in[4];
    const float* Wq    = (const float*)d_in[5];
    const float* bq    = (const float*)d_in[6];
    const float* Wk    = (const float*)d_in[7];
    const float* bk    = (const float*)d_in[8];
    const float* Wv    = (const float*)d_in[9];
    const float* bv    = (const float*)d_in[10];
    const float* Wo    = (const float*)d_in[11];
    const float* bo    = (const float*)d_in[12];
    const float* gamma = (const float*)d_in[13];
    const float* beta  = (const float*)d_in[14];
    float* out = (float*)d_out;

    float *qp, *kp, *vp, *ao;
    cudaGetSymbolAddress((void**)&qp, g_qp);
    cudaGetSymbolAddress((void**)&kp, g_kp);
    cudaGetSymbolAddress((void**)&vp, g_vp);
    cudaGetSymbolAddress((void**)&ao, g_ao);

    cudaFuncSetAttribute(attn_kernel,
                         cudaFuncAttributeMaxDynamicSharedMemorySize, ATTN_SMEM);

    dim3 gg(DD / 128, MM / 128);  // (8, 64)
    gemm_bf16x3<<<gg, 256>>>(q, Wq, bq, qp, MM, DD, DD);
    gemm_bf16x3<<<gg, 256>>>(k, Wk, bk, kp, MM, DD, DD);
    gemm_bf16x3<<<gg, 256>>>(v, Wv, bv, vp, MM, DD, DD);

    attn_kernel<<<dim3(SS / 64, HH, BB), 256, ATTN_SMEM>>>(qp, kp, vp, pad, ao);

    gemm_bf16x3<<<gg, 256>>>(ao, Wo, bo, qp, MM, DD, DD);

    ln_kernel<<<MM, 256>>>(q, qp, gamma, beta, out);
}

// round 3
// speedup vs baseline: 1.0989x; 1.0046x over previous
#include <cuda_runtime.h>
#include <cuda_bf16.h>
#include <cfloat>
#include <math.h>
#include <stdint.h>

// Problem constants
#define BB 4
#define SS 2048
#define DD 1024
#define HH 16
#define HD 64
#define MM (BB*SS)   // 8192

// Scratch (static device arrays; allocation-free per harness rules)
__device__ float g_qp[BB*SS*DD];  // Q projection; reused as Wo-GEMM output
__device__ float g_kp[BB*SS*DD];
__device__ float g_vp[BB*SS*DD];
__device__ float g_ao[BB*SS*DD];  // attention output

// ---------------------------------------------------------------------------
// Split-bf16 tensor-core GEMM (NT): C[M,N] = A[M,K] @ W[N,K]^T + bias[N]
// fp32 operands decomposed as hi(bf16)+lo(bf16); C ≈ hh + hl + lh (fp32 acc).
// 128x128 block, BK=32, 256 threads (8 warps), warp tile 32x64,
// mma.sync.aligned.m16n8k16.row.col.f32.bf16.bf16.f32
// ---------------------------------------------------------------------------
#define SMSTR 40   // smem row stride in halves (32 data + 8 pad)

#define MMA16816(d, a, b0v, b1v) \
    asm volatile("mma.sync.aligned.m16n8k16.row.col.f32.bf16.bf16.f32 " \
        "{%0,%1,%2,%3}, {%4,%5,%6,%7}, {%8,%9}, {%0,%1,%2,%3};\n" \
        : "+f"((d)[0]), "+f"((d)[1]), "+f"((d)[2]), "+f"((d)[3]) \
        : "r"((a)[0]), "r"((a)[1]), "r"((a)[2]), "r"((a)[3]), \
          "r"(b0v), "r"(b1v))

__device__ __forceinline__ void load_pack16(const float* __restrict__ g,
                                            uint32_t* __restrict__ p)
{
#pragma unroll
    for (int i = 0; i < 16; i += 4) {
        float4 v = *(const float4*)(g + i);
        float xs[4] = {v.x, v.y, v.z, v.w};
#pragma unroll
        for (int j = 0; j < 4; j++) {
            float x = xs[j];
            __nv_bfloat16 h = __float2bfloat16(x);
            float hf = __bfloat162float(h);
            __nv_bfloat16 l = __float2bfloat16(x - hf);
            p[i + j] = (uint32_t)__bfloat16_as_ushort(h)
                     | ((uint32_t)__bfloat16_as_ushort(l) << 16);
        }
    }
}

__global__ __launch_bounds__(256) void gemm_bf16x3(
    const float* __restrict__ A, const float* __restrict__ W,
    const float* __restrict__ bias, float* __restrict__ C,
    int M, int N, int K)
{
    __shared__ __nv_bfloat16 Ah[128][SMSTR], Al[128][SMSTR];
    __shared__ __nv_bfloat16 Wh[128][SMSTR], Wl[128][SMSTR];

    const int tid = threadIdx.x;
    const int bm = blockIdx.y * 128;
    const int bn = blockIdx.x * 128;
    const int lrow = tid >> 1;
    const int lcol = (tid & 1) * 16;

    const float* Ag = A + (size_t)(bm + lrow) * K + lcol;
    const float* Wg = W + (size_t)(bn + lrow) * K + lcol;

    const int warp = tid >> 5, lane = tid & 31;
    const int wm = (warp >> 1) * 32;   // warp M offset (4 warps along M)
    const int wn = (warp & 1) * 64;    // warp N offset (2 warps along N)
    const int lr = lane >> 2;          // 0..7
    const int lc2 = (lane & 3) * 2;    // 0,2,4,6

    float acc[2][8][4];
#pragma unroll
    for (int mi = 0; mi < 2; mi++)
#pragma unroll
        for (int ni = 0; ni < 8; ni++)
#pragma unroll
            for (int c = 0; c < 4; c++) acc[mi][ni][c] = 0.f;

    uint32_t pa[16], pw[16];
    load_pack16(Ag, pa);
    load_pack16(Wg, pw);

    for (int k0 = 0; k0 < K; k0 += 32) {
        // stage packed hi/lo into smem (u32 = two adjacent halves)
#pragma unroll
        for (int i = 0; i < 16; i += 2) {
            uint32_t ha = (pa[i] & 0xffffu) | (pa[i+1] << 16);
            uint32_t la = (pa[i] >> 16)     | (pa[i+1] & 0xffff0000u);
            uint32_t hw = (pw[i] & 0xffffu) | (pw[i+1] << 16);
            uint32_t lw = (pw[i] >> 16)     | (pw[i+1] & 0xffff0000u);
            *(uint32_t*)&Ah[lrow][lcol + i] = ha;
            *(uint32_t*)&Al[lrow][lcol + i] = la;
            *(uint32_t*)&Wh[lrow][lcol + i] = hw;
            *(uint32_t*)&Wl[lrow][lcol + i] = lw;
        }
        __syncthreads();

        if (k0 + 32 < K) {           // prefetch next slice
            load_pack16(Ag + k0 + 32, pa);
            load_pack16(Wg + k0 + 32, pw);
        }

#pragma unroll
        for (int kk = 0; kk < 32; kk += 16) {
            uint32_t ah[2][4], al[2][4];
#pragma unroll
            for (int mi = 0; mi < 2; mi++) {
                int r = wm + mi * 16 + lr;
                int c = kk + lc2;
                ah[mi][0] = *(const uint32_t*)&Ah[r    ][c    ];
                ah[mi][1] = *(const uint32_t*)&Ah[r + 8][c    ];
                ah[mi][2] = *(const uint32_t*)&Ah[r    ][c + 8];
                ah[mi][3] = *(const uint32_t*)&Ah[r + 8][c + 8];
                al[mi][0] = *(const uint32_t*)&Al[r    ][c    ];
                al[mi][1] = *(const uint32_t*)&Al[r + 8][c    ];
                al[mi][2] = *(const uint32_t*)&Al[r    ][c + 8];
                al[mi][3] = *(const uint32_t*)&Al[r + 8][c + 8];
            }
#pragma unroll
            for (int ni = 0; ni < 8; ni++) {
                int n = wn + ni * 8 + lr;
                int ck = kk + lc2;
                uint32_t bh0 = *(const uint32_t*)&Wh[n][ck    ];
                uint32_t bh1 = *(const uint32_t*)&Wh[n][ck + 8];
                uint32_t bl0 = *(const uint32_t*)&Wl[n][ck    ];
                uint32_t bl1 = *(const uint32_t*)&Wl[n][ck + 8];
#pragma unroll
                for (int mi = 0; mi < 2; mi++) {
                    MMA16816(acc[mi][ni], ah[mi], bh0, bh1);  // hi*hi
                    MMA16816(acc[mi][ni], al[mi], bh0, bh1);  // lo*hi
                    MMA16816(acc[mi][ni], ah[mi], bl0, bl1);  // hi*lo
                }
            }
        }
        __syncthreads();
    }

    // epilogue: fp32 + bias
#pragma unroll
    for (int mi = 0; mi < 2; mi++) {
#pragma unroll
        for (int ni = 0; ni < 8; ni++) {
            int row = bm + wm + mi * 16 + lr;
            int col = bn + wn + ni * 8 + lc2;
            float b0 = bias[col], b1 = bias[col + 1];
            float2 o0 = {acc[mi][ni][0] + b0, acc[mi][ni][1] + b1};
            float2 o1 = {acc[mi][ni][2] + b0, acc[mi][ni][3] + b1};
            *(float2*)(C + (size_t)row * N + col)       = o0;
            *(float2*)(C + (size_t)(row + 8) * N + col) = o1;
        }
    }
}

// ---------------------------------------------------------------------------
// Flash attention (fp32, causal + pad mask, scale folded into Q).
// Grid: (S/64, H, B). 256 threads. Thread (tx,ty) owns 4 rows (ty*4..),
// 4 keys (tx + 16*jj) for scores, 4 output cols (tx*4..) for PV.
// Dynamic smem: Qs[64][64] | Ks[64][68] | Vs[64][64] | Ps[64][68]
// ---------------------------------------------------------------------------
#define ATTN_SMEM ((64*64 + 64*68 + 64*64 + 64*68) * 4)

__global__ __launch_bounds__(256) void attn_kernel(
    const float* __restrict__ QP, const float* __restrict__ KP,
    const float* __restrict__ VP, const int* __restrict__ pad,
    float* __restrict__ O)
{
    extern __shared__ float smem[];
    float* Qs = smem;                 // [64][64]
    float* Ks = Qs + 64*64;           // [64][68]
    float* Vs = Ks + 64*68;           // [64][64]
    float* Ps = Vs + 64*64;           // [64][68]

    const int qt = blockIdx.x;
    const int h  = blockIdx.y;
    const int b  = blockIdx.z;
    const int tid = threadIdx.x;
    const int tx = tid & 15, ty = tid >> 4;
    const size_t base = (size_t)b * SS * DD + (size_t)h * SS * HD;
    const int* padb = pad + b * SS;

    for (int i = tid; i < 64*16; i += 256) {
        int r = i >> 4, c = (i & 15) << 2;
        float4 v = *(const float4*)(QP + base + (size_t)(qt*64 + r) * HD + c);
        v.x *= 0.125f; v.y *= 0.125f; v.z *= 0.125f; v.w *= 0.125f;
        *(float4*)(Qs + r*64 + c) = v;
    }

    float m[4], l[4], acc[4][4];
#pragma unroll
    for (int i = 0; i < 4; i++) {
        m[i] = -FLT_MAX; l[i] = 0.f;
#pragma unroll
        for (int c = 0; c < 4; c++) acc[i][c] = 0.f;
    }

    for (int j = 0; j <= qt; j++) {
        __syncthreads();
        for (int i = tid; i < 64*16; i += 256) {
            int r = i >> 4, c = (i & 15) << 2;
            float4 kv = *(const float4*)(KP + base + (size_t)(j*64 + r) * HD + c);
            float4 vv = *(const float4*)(VP + base + (size_t)(j*64 + r) * HD + c);
            *(float4*)(Ks + r*68 + c) = kv;
            *(float4*)(Vs + r*64 + c) = vv;
        }
        __syncthreads();

        float s[4][4];
#pragma unroll
        for (int i = 0; i < 4; i++)
#pragma unroll
            for (int jj = 0; jj < 4; jj++) s[i][jj] = 0.f;

#pragma unroll 4
        for (int d = 0; d < 64; d += 4) {
            float4 q4[4], k4[4];
#pragma unroll
            for (int i = 0; i < 4; i++)
                q4[i] = *(const float4*)(Qs + (ty*4 + i)*64 + d);
#pragma unroll
            for (int jj = 0; jj < 4; jj++)
                k4[jj] = *(const float4*)(Ks + (tx + jj*16)*68 + d);
#pragma unroll
            for (int i = 0; i < 4; i++)
#pragma unroll
                for (int jj = 0; jj < 4; jj++)
                    s[i][jj] += q4[i].x*k4[jj].x + q4[i].y*k4[jj].y
                              + q4[i].z*k4[jj].z + q4[i].w*k4[jj].w;
        }

#pragma unroll
        for (int jj = 0; jj < 4; jj++) {
            int kidx = j*64 + tx + jj*16;
            int pm = padb[kidx];
#pragma unroll
            for (int i = 0; i < 4; i++) {
                int qidx = qt*64 + ty*4 + i;
                if (pm == 0 || kidx > qidx) s[i][jj] = -FLT_MAX;
            }
        }

#pragma unroll
        for (int i = 0; i < 4; i++) {
            float mt = fmaxf(fmaxf(s[i][0], s[i][1]), fmaxf(s[i][2], s[i][3]));
#pragma unroll
            for (int o = 1; o < 16; o <<= 1)
                mt = fmaxf(mt, __shfl_xor_sync(0xffffffffu, mt, o));
            float mn = fmaxf(m[i], mt);
            float corr = __expf(m[i] - mn);
            float rs = 0.f;
#pragma unroll
            for (int jj = 0; jj < 4; jj++) {
                float p = __expf(s[i][jj] - mn);
                s[i][jj] = p;
                rs += p;
            }
#pragma unroll
            for (int o = 1; o < 16; o <<= 1)
                rs += __shfl_xor_sync(0xffffffffu, rs, o);
            l[i] = l[i] * corr + rs;
            m[i] = mn;
#pragma unroll
            for (int c = 0; c < 4; c++) acc[i][c] *= corr;
        }

#pragma unroll
        for (int jj = 0; jj < 4; jj++)
#pragma unroll
            for (int i = 0; i < 4; i++)
                Ps[(tx + jj*16)*68 + ty*4 + i] = s[i][jj];
        __syncthreads();

#pragma unroll 8
        for (int key = 0; key < 64; key++) {
            float4 pr = *(const float4*)(Ps + key*68 + ty*4);
            float4 vv = *(const float4*)(Vs + key*64 + tx*4);
            float p4[4] = {pr.x, pr.y, pr.z, pr.w};
            float v4[4] = {vv.x, vv.y, vv.z, vv.w};
#pragma unroll
            for (int i = 0; i < 4; i++)
#pragma unroll
                for (int c = 0; c < 4; c++)
                    acc[i][c] += p4[i] * v4[c];
        }
    }

#pragma unroll
    for (int i = 0; i < 4; i++) {
        float inv = 1.f / l[i];
        float4 o;
        o.x = acc[i][0] * inv;
        o.y = acc[i][1] * inv;
        o.z = acc[i][2] * inv;
        o.w = acc[i][3] * inv;
        *(float4*)(O + base + (size_t)(qt*64 + ty*4 + i) * HD + tx*4) = o;
    }
}

// ---------------------------------------------------------------------------
// Residual add + LayerNorm
// ---------------------------------------------------------------------------
__global__ __launch_bounds__(256) void ln_kernel(
    const float* __restrict__ X, const float* __restrict__ Yo,
    const float* __restrict__ gamma, const float* __restrict__ beta,
    float* __restrict__ out)
{
    const int row = blockIdx.x;
    const int tid = threadIdx.x;
    const size_t off = (size_t)row * DD + tid * 4;
    float4 xv = *(const float4*)(X + off);
    float4 yv = *(const float4*)(Yo + off);
    float v[4] = {xv.x + yv.x, xv.y + yv.y, xv.z + yv.z, xv.w + yv.w};
    float s  = v[0] + v[1] + v[2] + v[3];
    float sq = v[0]*v[0] + v[1]*v[1] + v[2]*v[2] + v[3]*v[3];
#pragma unroll
    for (int o = 16; o; o >>= 1) {
        s  += __shfl_xor_sync(0xffffffffu, s,  o);
        sq += __shfl_xor_sync(0xffffffffu, sq, o);
    }
    __shared__ float ssum[8], ssq[8];
    if ((tid & 31) == 0) { ssum[tid >> 5] = s; ssq[tid >> 5] = sq; }
    __syncthreads();
    s = 0.f; sq = 0.f;
#pragma unroll
    for (int i = 0; i < 8; i++) { s += ssum[i]; sq += ssq[i]; }
    float mean = s * (1.f / DD);
    float var  = sq * (1.f / DD) - mean * mean;
    float rstd = 1.f / (sqrtf(fmaxf(var, 0.f)) + 1e-8f);
    int c = tid * 4;
    float4 g  = *(const float4*)(gamma + c);
    float4 bt = *(const float4*)(beta + c);
    float4 o;
    o.x = g.x * (v[0] - mean) * rstd + bt.x;
    o.y = g.y * (v[1] - mean) * rstd + bt.y;
    o.z = g.z * (v[2] - mean) * rstd + bt.z;
    o.w = g.w * (v[3] - mean) * rstd + bt.w;
    *(float4*)(out + off) = o;
}

// ---------------------------------------------------------------------------
extern "C" void kernel_launch(void* const* d_in, const int* in_sizes, int n_in,
                              void* d_out, int out_size)
{
    const float* q     = (const float*)d_in[0];
    const float* k     = (const float*)d_in[1];
    const float* v     = (const float*)d_in[2];
    // d_in[3] = attn_mask (deterministic causal tril) — computed analytically
    const int*   pad   = (const int*)d_in[4];
    const float* Wq    = (const float*)d_in[5];
    const float* bq    = (const float*)d_in[6];
    const float* Wk    = (const float*)d_in[7];
    const float* bk    = (const float*)d_in[8];
    const float* Wv    = (const float*)d_in[9];
    const float* bv    = (const float*)d_in[10];
    const float* Wo    = (const float*)d_in[11];
    const float* bo    = (const float*)d_in[12];
    const float* gamma = (const float*)d_in[13];
    const float* beta  = (const float*)d_in[14];
    float* out = (float*)d_out;

    float *qp, *kp, *vp, *ao;
    cudaGetSymbolAddress((void**)&qp, g_qp);
    cudaGetSymbolAddress((void**)&kp, g_kp);
    cudaGetSymbolAddress((void**)&vp, g_vp);
    cudaGetSymbolAddress((void**)&ao, g_ao);

    cudaFuncSetAttribute(attn_kernel,
                         cudaFuncAttributeMaxDynamicSharedMemorySize, ATTN_SMEM);

    dim3 gg(DD / 128, MM / 128);  // (8, 64)
    gemm_bf16x3<<<gg, 256>>>(q, Wq, bq, qp, MM, DD, DD);
    gemm_bf16x3<<<gg, 256>>>(k, Wk, bk, kp, MM, DD, DD);
    gemm_bf16x3<<<gg, 256>>>(v, Wv, bv, vp, MM, DD, DD);

    attn_kernel<<<dim3(SS / 64, HH, BB), 256, ATTN_SMEM>>>(qp, kp, vp, pad, ao);

    gemm_bf16x3<<<gg, 256>>>(ao, Wo, bo, qp, MM, DD, DD);

    ln_kernel<<<MM, 256>>>(q, qp, gamma, beta, out);
}